// round 13
// baseline (speedup 1.0000x reference)
#include <cuda_runtime.h>
#include <cuda_fp16.h>

#define N_NODES 100000
#define N_EDGES 1600000
#define M_TOTAL (N_EDGES + N_NODES)
#define HD 128
#define NHEAD 4
#define NB ((N_NODES + 255) / 256)      // 391 scan blocks
#define NSTRIP ((N_NODES + 127) / 128)  // 782 gemm strips
#define GEMM_GRID 444                   // 3 blocks/SM

// ---- scratch (device globals: the sanctioned no-alloc path) ----
__device__ __half g_h[N_NODES * HD];       // 25.6 MB transformed features (fp16)
__device__ float  g_asrc[N_NODES * NHEAD];
__device__ float  g_adst[N_NODES * NHEAD];
__device__ float  g_u[HD * 8];             // u[k][j]: j<4 -> src head j, j>=4 -> dst head j-4
__device__ int    g_deg[N_NODES];          // BSS-zeroed at load; re-zeroed by scanC each call
__device__ int    g_off[N_NODES + 1];      // CSR row offsets (by dst)
__device__ int    g_pos[N_NODES];          // scatter cursors
__device__ int    g_srcs[M_TOTAL];         // src ids grouped by dst
__device__ int    g_bsum[512];             // scan block sums

__device__ __forceinline__ float leaky(float e) { return e > 0.f ? e : 0.2f * e; }

__device__ __forceinline__ unsigned tf32(float f)
{
    unsigned u;
    asm("cvt.rna.tf32.f32 %0, %1;" : "=r"(u) : "f"(f));
    return u;
}

// ============================================================================
// K_gemm_tc: h = x @ W via mma.sync.m16n8k8.tf32, persistent strip loop.
// Changes this round: 3 blocks/SM (occ 32%->48%) and the degree count is
// INTERLEAVED into the strip loop (chunk per strip-iteration) so its LDG/RED
// latency hides under other warps' MMAs instead of serializing as a prologue.
// W staged once per block in smem stride-136 (conflict-free B-frag LDS);
// A-frags register double-buffered. Fused u = W@att (block 0). h stored fp16.
// ============================================================================
extern __shared__ float tc_smem[];  // Ws[128][136]
__global__ void __launch_bounds__(256, 3) k_gemm_tc(
    const float* __restrict__ x, const float* __restrict__ W,
    const float* __restrict__ att_src, const float* __restrict__ att_dst,
    const int* __restrict__ ei)
{
    float* Ws = tc_smem;
    const int t = threadIdx.x, warp = t >> 5, lane = t & 31;

    // fused u = W @ att (block 0 only; consumed by k_logits later)
    if (blockIdx.x == 0) {
        for (int e = t; e < HD * 8; e += 256) {
            int k = e >> 3, j = e & 7;
            int head = j & 3;
            const float* att = (j < 4) ? att_src : att_dst;
            float s = 0.f;
#pragma unroll
            for (int d = 0; d < 32; d++)
                s = fmaf(W[k * HD + head * 32 + d], att[head * 32 + d], s);
            g_u[k * 8 + j] = s;
        }
    }

    // stage W as tf32 bit patterns (once per block; read-only afterwards)
    for (int i = t; i < HD * HD; i += 256) {
        int k = i >> 7, c = i & 127;
        Ws[k * 136 + c] = __uint_as_float(tf32(W[i]));
    }
    __syncthreads();

    // degree-count work partition: this block's edge range, sliced per strip-iter
    const int nIt = (NSTRIP - blockIdx.x + GEMM_GRID - 1) / GEMM_GRID;
    const int EPB = (N_EDGES + GEMM_GRID - 1) / GEMM_GRID;
    const int estart = blockIdx.x * EPB;
    const int eend = min(estart + EPB, N_EDGES);
    const int echunk = (eend - estart + nIt - 1) / nIt;

    const int qa = lane & 3;
    const int cb = lane >> 2;

    int it = 0;
    for (int strip = blockIdx.x; strip < NSTRIP; strip += GEMM_GRID, it++) {
        // interleaved degree-count chunk (independent of MMA dataflow; its
        // LDG->RED stalls are covered by other warps' tensor work)
        {
            const int c0 = estart + it * echunk;
            const int c1 = min(c0 + echunk, eend);
            for (int m = c0 + t; m < c1; m += 256)
                atomicAdd(&g_deg[ei[N_EDGES + m]], 1);
        }

        const int ra = strip * 128 + warp * 16 + (lane >> 2);  // rows ra, ra+8
        const bool v0 = ra < N_NODES, v1 = (ra + 8) < N_NODES;
        const float* p0 = x + (long long)ra * HD + qa;
        const float* p1 = p0 + 8 * HD;

        float acc[16][4];
#pragma unroll
        for (int nt = 0; nt < 16; nt++)
#pragma unroll
            for (int q = 0; q < 4; q++) acc[nt][q] = 0.f;

        // prime k0 = 0
        unsigned ac0 = 0, ac1 = 0, ac2 = 0, ac3 = 0;
        if (v0) { ac0 = tf32(p0[0]); ac2 = tf32(p0[4]); }
        if (v1) { ac1 = tf32(p1[0]); ac3 = tf32(p1[4]); }

        for (int k0 = 0; k0 < HD; k0 += 8) {
            // prefetch next k-step BEFORE the MMA chain (double buffer)
            unsigned an0 = 0, an1 = 0, an2 = 0, an3 = 0;
            if (k0 + 8 < HD) {
                if (v0) { an0 = tf32(p0[k0 + 8]); an2 = tf32(p0[k0 + 12]); }
                if (v1) { an1 = tf32(p1[k0 + 8]); an3 = tf32(p1[k0 + 12]); }
            }
            const int kb = k0 + qa;
#pragma unroll
            for (int nt = 0; nt < 16; nt++) {
                unsigned b0 = __float_as_uint(Ws[kb * 136 + nt * 8 + cb]);
                unsigned b1 = __float_as_uint(Ws[(kb + 4) * 136 + nt * 8 + cb]);
                asm volatile(
                    "mma.sync.aligned.m16n8k8.row.col.f32.tf32.tf32.f32 "
                    "{%0,%1,%2,%3}, {%4,%5,%6,%7}, {%8,%9}, {%0,%1,%2,%3};"
                    : "+f"(acc[nt][0]), "+f"(acc[nt][1]), "+f"(acc[nt][2]), "+f"(acc[nt][3])
                    : "r"(ac0), "r"(ac1), "r"(ac2), "r"(ac3), "r"(b0), "r"(b1));
            }
            ac0 = an0; ac1 = an1; ac2 = an2; ac3 = an3;
        }

        // store h fp16: c0,c1 -> (ra, col..col+1); c2,c3 -> (ra+8, same cols)
#pragma unroll
        for (int nt = 0; nt < 16; nt++) {
            const int col = nt * 8 + 2 * qa;
            if (v0)
                *(__half2*)(g_h + (long long)ra * HD + col) =
                    __floats2half2_rn(acc[nt][0], acc[nt][1]);
            if (v1)
                *(__half2*)(g_h + (long long)(ra + 8) * HD + col) =
                    __floats2half2_rn(acc[nt][2], acc[nt][3]);
        }
    }
}

// ============================================================================
// CSR build: block scan -> (block-prefix + apply + deg rezero) -> scatter
// ============================================================================
__global__ void k_scanA()
{
    __shared__ int s[256];
    int t = threadIdx.x;
    int i = blockIdx.x * 256 + t;
    int v = (i < N_NODES) ? (g_deg[i] + 1) : 0;   // +1 = self loop
    s[t] = v;
    __syncthreads();
#pragma unroll
    for (int off = 1; off < 256; off <<= 1) {
        int u = (t >= off) ? s[t - off] : 0;
        __syncthreads();
        s[t] += u;
        __syncthreads();
    }
    if (i < N_NODES) g_off[i] = s[t] - v;       // exclusive within block
    if (t == 255) g_bsum[blockIdx.x] = s[255];  // block total
}

__global__ void k_scanC()  // global block-prefix + apply; rezero g_deg for next call
{
    __shared__ int pref;
    int t = threadIdx.x;
    if (t < 32) {
        int s = 0;
        for (int i = t; i < blockIdx.x; i += 32) s += g_bsum[i];
#pragma unroll
        for (int o = 16; o; o >>= 1) s += __shfl_xor_sync(0xffffffffu, s, o);
        if (t == 0) pref = s;
    }
    __syncthreads();
    int i = blockIdx.x * 256 + t;
    if (i < N_NODES) {
        int o = g_off[i] + pref;
        g_off[i] = o;
        g_pos[i] = o;
        g_deg[i] = 0;                            // ready for next kernel_launch call
    }
    if (i == 0) g_off[N_NODES] = M_TOTAL;
}

__global__ void k_scatter(const int* __restrict__ ei)   // launch idx 3 -> profiled
{
    int m = blockIdx.x * blockDim.x + threadIdx.x;
    if (m >= M_TOTAL) return;
    int src, dst;
    if (m < N_EDGES) { src = ei[m]; dst = ei[N_EDGES + m]; }
    else             { src = dst = m - N_EDGES; }
    int p = atomicAdd(&g_pos[dst], 1);
    g_srcs[p] = src;
}

// ============================================================================
// K_logits: a = x @ u  (exact fp32 logits; keeps the exp path off tf32).
// ============================================================================
__global__ void k_logits(const float* __restrict__ x)
{
    int gid = blockIdx.x * blockDim.x + threadIdx.x;
    if (gid >= N_NODES * 8) return;
    int n = gid >> 3, j = gid & 7;
    const float4* xr = (const float4*)(x + (long long)n * HD);
    float s = 0.f;
#pragma unroll 8
    for (int k = 0; k < 32; k++) {
        float4 xv = __ldg(&xr[k]);
        s = fmaf(xv.x, __ldg(&g_u[(k * 4 + 0) * 8 + j]),
            fmaf(xv.y, __ldg(&g_u[(k * 4 + 1) * 8 + j]),
            fmaf(xv.z, __ldg(&g_u[(k * 4 + 2) * 8 + j]),
            fmaf(xv.w, __ldg(&g_u[(k * 4 + 3) * 8 + j]), s))));
    }
    if (j < 4) g_asrc[n * NHEAD + j] = s;
    else       g_adst[n * NHEAD + (j - 4)] = s;
}

// ============================================================================
// K_agg: one warp per dst node, half-warp per edge (2 edges/iter), DEPTH-2
// pipeline over pairs -> 4 edges in flight per warp. Lane = 16*half + q;
// q owns channels [8q,8q+8) -> head q>>2; LDG.128 16B/lane. alpha without
// max-shift (softmax shift-invariant; |logit| small). fp32 accumulate,
// cross-half shfl reduce, normalize+bias+ELU, two float4 stores.
// ============================================================================
__global__ void k_agg(const float* __restrict__ bias, float* __restrict__ out)
{
    int n = (blockIdx.x * blockDim.x + threadIdx.x) >> 5;
    int lane = threadIdx.x & 31;
    if (n >= N_NODES) return;
    const int half = lane >> 4;     // which edge of the pair
    const int q = lane & 15;        // channel group: channels 8q..8q+7
    const int head = q >> 2;
    const float adh = g_adst[n * NHEAD + head];

    const int row = g_off[n];
    const int end = g_off[n + 1];

    float acc[8];
#pragma unroll
    for (int p = 0; p < 8; p++) acc[p] = 0.f;
    float denom = 0.f;

    for (int base = row; base < end; base += 32) {
        const int cnt = min(32, end - base);
        int s_reg = (lane < cnt) ? g_srcs[base + lane] : 0;

        bool val[2];
        float as[2];
        uint4 hu[2];
#define AGG_PRIME(slot, jj)                                                     \
        do {                                                                    \
            const int e_ = (jj) + half;                                         \
            val[slot] = e_ < cnt;                                               \
            int idx_ = val[slot] ? e_ : 0;                                      \
            int src_ = __shfl_sync(0xffffffffu, s_reg, idx_);                   \
            as[slot] = __ldg(&g_asrc[src_ * NHEAD + head]);                     \
            hu[slot] = *(const uint4*)(g_h + (long long)src_ * HD + q * 8);     \
        } while (0)

        AGG_PRIME(0, 0);
        AGG_PRIME(1, 2);

#pragma unroll 2
        for (int j = 0; j < cnt; j += 2) {
            const int slot = (j >> 1) & 1;
            float ex = val[slot] ? __expf(leaky(as[slot] + adh)) : 0.f;
            uint4 hc = hu[slot];
            if (j + 4 < cnt) AGG_PRIME(slot, j + 4);  // refill before the use gap
            denom += ex;
            const __half2* hp = (const __half2*)&hc;
#pragma unroll
            for (int p = 0; p < 4; p++) {
                float2 f = __half22float2(hp[p]);
                acc[2 * p]     = fmaf(ex, f.x, acc[2 * p]);
                acc[2 * p + 1] = fmaf(ex, f.y, acc[2 * p + 1]);
            }
        }
#undef AGG_PRIME
    }

    // cross-half reduction (both halves end with the full sums)
    denom += __shfl_xor_sync(0xffffffffu, denom, 16);
#pragma unroll
    for (int p = 0; p < 8; p++) acc[p] += __shfl_xor_sync(0xffffffffu, acc[p], 16);

    if (half == 0) {
        const float inv = 1.f / (denom + 1e-16f);
        float4 b0 = ((const float4*)bias)[q * 2];
        float4 b1 = ((const float4*)bias)[q * 2 + 1];
        float4 o0, o1;
        o0.x = acc[0] * inv + b0.x; o0.y = acc[1] * inv + b0.y;
        o0.z = acc[2] * inv + b0.z; o0.w = acc[3] * inv + b0.w;
        o1.x = acc[4] * inv + b1.x; o1.y = acc[5] * inv + b1.y;
        o1.z = acc[6] * inv + b1.z; o1.w = acc[7] * inv + b1.w;
        o0.x = o0.x > 0.f ? o0.x : expm1f(o0.x);
        o0.y = o0.y > 0.f ? o0.y : expm1f(o0.y);
        o0.z = o0.z > 0.f ? o0.z : expm1f(o0.z);
        o0.w = o0.w > 0.f ? o0.w : expm1f(o0.w);
        o1.x = o1.x > 0.f ? o1.x : expm1f(o1.x);
        o1.y = o1.y > 0.f ? o1.y : expm1f(o1.y);
        o1.z = o1.z > 0.f ? o1.z : expm1f(o1.z);
        o1.w = o1.w > 0.f ? o1.w : expm1f(o1.w);
        float4* op = (float4*)(out + (long long)n * HD + q * 8);
        op[0] = o0;
        op[1] = o1;
    }
}

// ============================================================================
extern "C" void kernel_launch(void* const* d_in, const int* in_sizes, int n_in,
                              void* d_out, int out_size)
{
    const float* x    = (const float*)d_in[0];
    const int*   ei   = (const int*)d_in[1];     // int32 (JAX x64 disabled)
    const float* W    = (const float*)d_in[2];
    const float* aS   = (const float*)d_in[3];
    const float* aD   = (const float*)d_in[4];
    const float* bias = (const float*)d_in[5];
    float*       out  = (float*)d_out;

    const int tc_smem_bytes = 128 * 136 * (int)sizeof(float);  // 69632 B
    cudaFuncSetAttribute(k_gemm_tc, cudaFuncAttributeMaxDynamicSharedMemorySize,
                         tc_smem_bytes);

    k_gemm_tc<<<GEMM_GRID, 256, tc_smem_bytes>>>(x, W, aS, aD, ei);  // idx 0
    k_scanA<<<NB, 256>>>();                                          // idx 1
    k_scanC<<<NB, 256>>>();                                          // idx 2
    k_scatter<<<(M_TOTAL + 255) / 256, 256>>>(ei);                   // idx 3 (profiled)
    k_logits<<<(N_NODES * 8 + 255) / 256, 256>>>(x);                 // idx 4
    k_agg<<<(N_NODES * 32 + 255) / 256, 256>>>(bias, out);           // idx 5
}

// round 15
// speedup vs baseline: 1.4898x; 1.4898x over previous
#include <cuda_runtime.h>
#include <cuda_fp16.h>

#define N_NODES 100000
#define N_EDGES 1600000
#define HD 128
#define NHEAD 4
#define NB ((N_NODES + 255) / 256)      // 391 scan blocks
#define NSTRIP ((N_NODES + 127) / 128)  // 782 gemm strips

// ---- scratch (device globals: the sanctioned no-alloc path) ----
__device__ __half g_h[N_NODES * HD];       // 25.6 MB transformed features (fp16)
__device__ float  g_asrc[N_NODES * NHEAD];
__device__ float  g_adst[N_NODES * NHEAD];
__device__ float  g_u[HD * 8];             // u[k][j]: j<4 -> src head j, j>=4 -> dst head j-4
__device__ int    g_deg[N_NODES];          // BSS-zeroed at load; re-zeroed by scanC each call
__device__ int    g_off[N_NODES + 1];      // CSR row offsets (by dst), REAL edges only
__device__ int    g_pos[N_NODES];          // scatter cursors
__device__ int    g_srcs[N_EDGES];         // src ids grouped by dst
__device__ int    g_bsum[512];             // scan block sums

__device__ __forceinline__ float leaky(float e) { return e > 0.f ? e : 0.2f * e; }

__device__ __forceinline__ unsigned tf32(float f)
{
    unsigned u;
    asm("cvt.rna.tf32.f32 %0, %1;" : "=r"(u) : "f"(f));
    return u;
}

// ============================================================================
// K_gemm_tc (R11-proven): h = x @ W via mma.sync.m16n8k8.tf32, persistent
// strip loop, A-frags register double-buffered, W staged once per block in
// smem stride-136 (conflict-free B-frag LDS). Fused: degree count prologue +
// u = W@att (block 0). h stored fp16. 2 blocks/SM (3 causes spills - R13).
// ============================================================================
extern __shared__ float tc_smem[];  // Ws[128][136]
__global__ void __launch_bounds__(256, 2) k_gemm_tc(
    const float* __restrict__ x, const float* __restrict__ W,
    const float* __restrict__ att_src, const float* __restrict__ att_dst,
    const int* __restrict__ ei)
{
    float* Ws = tc_smem;
    const int t = threadIdx.x, warp = t >> 5, lane = t & 31;

    // fused degree count (edges only; self-loops handled analytically in agg)
    for (int m = blockIdx.x * blockDim.x + t; m < N_EDGES; m += gridDim.x * blockDim.x)
        atomicAdd(&g_deg[ei[N_EDGES + m]], 1);

    // fused u = W @ att (block 0 only; consumed by the fused scatter+logits)
    if (blockIdx.x == 0) {
        for (int e = t; e < HD * 8; e += 256) {
            int k = e >> 3, j = e & 7;
            int head = j & 3;
            const float* att = (j < 4) ? att_src : att_dst;
            float s = 0.f;
#pragma unroll
            for (int d = 0; d < 32; d++)
                s = fmaf(W[k * HD + head * 32 + d], att[head * 32 + d], s);
            g_u[k * 8 + j] = s;
        }
    }

    // stage W as tf32 bit patterns (once per block; read-only afterwards)
    for (int i = t; i < HD * HD; i += 256) {
        int k = i >> 7, c = i & 127;
        Ws[k * 136 + c] = __uint_as_float(tf32(W[i]));
    }
    __syncthreads();

    const int qa = lane & 3;
    const int cb = lane >> 2;

    for (int strip = blockIdx.x; strip < NSTRIP; strip += gridDim.x) {
        const int ra = strip * 128 + warp * 16 + (lane >> 2);  // rows ra, ra+8
        const bool v0 = ra < N_NODES, v1 = (ra + 8) < N_NODES;
        const float* p0 = x + (long long)ra * HD + qa;
        const float* p1 = p0 + 8 * HD;

        float acc[16][4];
#pragma unroll
        for (int nt = 0; nt < 16; nt++)
#pragma unroll
            for (int q = 0; q < 4; q++) acc[nt][q] = 0.f;

        // prime k0 = 0
        unsigned ac0 = 0, ac1 = 0, ac2 = 0, ac3 = 0;
        if (v0) { ac0 = tf32(p0[0]); ac2 = tf32(p0[4]); }
        if (v1) { ac1 = tf32(p1[0]); ac3 = tf32(p1[4]); }

        for (int k0 = 0; k0 < HD; k0 += 8) {
            // prefetch next k-step BEFORE the MMA chain (double buffer)
            unsigned an0 = 0, an1 = 0, an2 = 0, an3 = 0;
            if (k0 + 8 < HD) {
                if (v0) { an0 = tf32(p0[k0 + 8]); an2 = tf32(p0[k0 + 12]); }
                if (v1) { an1 = tf32(p1[k0 + 8]); an3 = tf32(p1[k0 + 12]); }
            }
            const int kb = k0 + qa;
#pragma unroll
            for (int nt = 0; nt < 16; nt++) {
                unsigned b0 = __float_as_uint(Ws[kb * 136 + nt * 8 + cb]);
                unsigned b1 = __float_as_uint(Ws[(kb + 4) * 136 + nt * 8 + cb]);
                asm volatile(
                    "mma.sync.aligned.m16n8k8.row.col.f32.tf32.tf32.f32 "
                    "{%0,%1,%2,%3}, {%4,%5,%6,%7}, {%8,%9}, {%0,%1,%2,%3};"
                    : "+f"(acc[nt][0]), "+f"(acc[nt][1]), "+f"(acc[nt][2]), "+f"(acc[nt][3])
                    : "r"(ac0), "r"(ac1), "r"(ac2), "r"(ac3), "r"(b0), "r"(b1));
            }
            ac0 = an0; ac1 = an1; ac2 = an2; ac3 = an3;
        }

        // store h fp16: c0,c1 -> (ra, col..col+1); c2,c3 -> (ra+8, same cols)
#pragma unroll
        for (int nt = 0; nt < 16; nt++) {
            const int col = nt * 8 + 2 * qa;
            if (v0)
                *(__half2*)(g_h + (long long)ra * HD + col) =
                    __floats2half2_rn(acc[nt][0], acc[nt][1]);
            if (v1)
                *(__half2*)(g_h + (long long)(ra + 8) * HD + col) =
                    __floats2half2_rn(acc[nt][2], acc[nt][3]);
        }
    }
}

// ============================================================================
// CSR build over REAL edges: block scan -> (block-prefix + apply + rezero) ->
// scatter (with logits fused into its idle issue slots).
// ============================================================================
__global__ void k_scanA()
{
    __shared__ int s[256];
    int t = threadIdx.x;
    int i = blockIdx.x * 256 + t;
    int v = (i < N_NODES) ? g_deg[i] : 0;
    s[t] = v;
    __syncthreads();
#pragma unroll
    for (int off = 1; off < 256; off <<= 1) {
        int u = (t >= off) ? s[t - off] : 0;
        __syncthreads();
        s[t] += u;
        __syncthreads();
    }
    if (i < N_NODES) g_off[i] = s[t] - v;       // exclusive within block
    if (t == 255) g_bsum[blockIdx.x] = s[255];  // block total
}

__global__ void k_scanC()  // global block-prefix + apply; rezero g_deg for next call
{
    __shared__ int pref;
    int t = threadIdx.x;
    if (t < 32) {
        int s = 0;
        for (int i = t; i < blockIdx.x; i += 32) s += g_bsum[i];
#pragma unroll
        for (int o = 16; o; o >>= 1) s += __shfl_xor_sync(0xffffffffu, s, o);
        if (t == 0) pref = s;
    }
    __syncthreads();
    int i = blockIdx.x * 256 + t;
    if (i < N_NODES) {
        int o = g_off[i] + pref;
        g_off[i] = o;
        g_pos[i] = o;
        g_deg[i] = 0;                            // ready for next kernel_launch call
    }
    if (i == 0) g_off[N_NODES] = N_EDGES;
}

// Scatter (atomic-latency-bound, issue 5.5%) + FUSED exact-fp32 logits
// (a = x @ u) filling the idle issue slots. Launch idx 3 -> profiled.
__global__ void k_scatter(const int* __restrict__ ei, const float* __restrict__ x)
{
    int m = blockIdx.x * blockDim.x + threadIdx.x;
    if (m < N_EDGES) {
        int src = ei[m], dst = ei[N_EDGES + m];
        int p = atomicAdd(&g_pos[dst], 1);
        g_srcs[p] = src;
    }
    if (m < N_NODES * 8) {
        int n = m >> 3, j = m & 7;
        const float4* xr = (const float4*)(x + (long long)n * HD);
        float s = 0.f;
#pragma unroll 8
        for (int k = 0; k < 32; k++) {
            float4 xv = __ldg(&xr[k]);
            s = fmaf(xv.x, __ldg(&g_u[(k * 4 + 0) * 8 + j]),
                fmaf(xv.y, __ldg(&g_u[(k * 4 + 1) * 8 + j]),
                fmaf(xv.z, __ldg(&g_u[(k * 4 + 2) * 8 + j]),
                fmaf(xv.w, __ldg(&g_u[(k * 4 + 3) * 8 + j]), s))));
        }
        if (j < 4) g_asrc[n * NHEAD + j] = s;
        else       g_adst[n * NHEAD + (j - 4)] = s;
    }
}

// ============================================================================
// K_agg (R11-proven pair form): one warp per dst node, half-warp per edge
// (2 edges/iter), depth-1 prefetch. Lane = 16*half + q; q owns channels
// [8q,8q+8) -> head q>>2; LDG.128 16B/lane. Self-loop handled analytically:
// half 0 initializes denom/acc with exp(leaky(asrc[n]+adst[n])) * h[n].
// alpha without max-shift (softmax shift-invariant; |logit| small).
// fp32 accumulate, cross-half shfl reduce, normalize+bias+ELU, 2 stores.
// ============================================================================
__global__ void k_agg(const float* __restrict__ bias, float* __restrict__ out)
{
    int n = (blockIdx.x * blockDim.x + threadIdx.x) >> 5;
    int lane = threadIdx.x & 31;
    if (n >= N_NODES) return;
    const int half = lane >> 4;     // which edge of the pair
    const int q = lane & 15;        // channel group: channels 8q..8q+7
    const int head = q >> 2;
    const float adh = g_adst[n * NHEAD + head];

    const int row = g_off[n];
    const int end = g_off[n + 1];

    float acc[8];
    float denom;
    if (half == 0) {
        // analytic self-loop: weight exp(leaky(asrc[n] + adst[n])) on h[n]
        float ex0 = __expf(leaky(g_asrc[n * NHEAD + head] + adh));
        denom = ex0;
        uint4 own = *(const uint4*)(g_h + (long long)n * HD + q * 8);
        const __half2* op = (const __half2*)&own;
#pragma unroll
        for (int p = 0; p < 4; p++) {
            float2 f = __half22float2(op[p]);
            acc[2 * p]     = ex0 * f.x;
            acc[2 * p + 1] = ex0 * f.y;
        }
    } else {
        denom = 0.f;
#pragma unroll
        for (int p = 0; p < 8; p++) acc[p] = 0.f;
    }

    for (int base = row; base < end; base += 32) {
        const int cnt = min(32, end - base);
        int s_reg = (lane < cnt) ? g_srcs[base + lane] : 0;

        // prime pair 0: this half handles edge j = half
        bool val_c = half < cnt;
        int idx_c = val_c ? half : 0;
        int src_c = __shfl_sync(0xffffffffu, s_reg, idx_c);
        float as_c = __ldg(&g_asrc[src_c * NHEAD + head]);
        uint4 hu_c = *(const uint4*)(g_h + (long long)src_c * HD + q * 8);

        for (int j = 0; j < cnt; j += 2) {
            // prefetch next pair
            const int jn = j + 2 + half;
            const bool val_n = jn < cnt;
            float as_n = 0.f;
            uint4 hu_n = make_uint4(0, 0, 0, 0);
            if (j + 2 < cnt) {
                int idx_n = val_n ? jn : 0;
                int src_n = __shfl_sync(0xffffffffu, s_reg, idx_n);
                as_n = __ldg(&g_asrc[src_n * NHEAD + head]);
                hu_n = *(const uint4*)(g_h + (long long)src_n * HD + q * 8);
            }
            float ex = val_c ? __expf(leaky(as_c + adh)) : 0.f;
            denom += ex;
            const __half2* hp = (const __half2*)&hu_c;
#pragma unroll
            for (int p = 0; p < 4; p++) {
                float2 f = __half22float2(hp[p]);
                acc[2 * p]     = fmaf(ex, f.x, acc[2 * p]);
                acc[2 * p + 1] = fmaf(ex, f.y, acc[2 * p + 1]);
            }
            val_c = val_n; as_c = as_n; hu_c = hu_n;
        }
    }

    // cross-half reduction (both halves end with the full sums)
    denom += __shfl_xor_sync(0xffffffffu, denom, 16);
#pragma unroll
    for (int p = 0; p < 8; p++) acc[p] += __shfl_xor_sync(0xffffffffu, acc[p], 16);

    if (half == 0) {
        const float inv = 1.f / (denom + 1e-16f);
        float4 b0 = ((const float4*)bias)[q * 2];
        float4 b1 = ((const float4*)bias)[q * 2 + 1];
        float4 o0, o1;
        o0.x = acc[0] * inv + b0.x; o0.y = acc[1] * inv + b0.y;
        o0.z = acc[2] * inv + b0.z; o0.w = acc[3] * inv + b0.w;
        o1.x = acc[4] * inv + b1.x; o1.y = acc[5] * inv + b1.y;
        o1.z = acc[6] * inv + b1.z; o1.w = acc[7] * inv + b1.w;
        o0.x = o0.x > 0.f ? o0.x : expm1f(o0.x);
        o0.y = o0.y > 0.f ? o0.y : expm1f(o0.y);
        o0.z = o0.z > 0.f ? o0.z : expm1f(o0.z);
        o0.w = o0.w > 0.f ? o0.w : expm1f(o0.w);
        o1.x = o1.x > 0.f ? o1.x : expm1f(o1.x);
        o1.y = o1.y > 0.f ? o1.y : expm1f(o1.y);
        o1.z = o1.z > 0.f ? o1.z : expm1f(o1.z);
        o1.w = o1.w > 0.f ? o1.w : expm1f(o1.w);
        float4* op = (float4*)(out + (long long)n * HD + q * 8);
        op[0] = o0;
        op[1] = o1;
    }
}

// ============================================================================
extern "C" void kernel_launch(void* const* d_in, const int* in_sizes, int n_in,
                              void* d_out, int out_size)
{
    const float* x    = (const float*)d_in[0];
    const int*   ei   = (const int*)d_in[1];     // int32 (JAX x64 disabled)
    const float* W    = (const float*)d_in[2];
    const float* aS   = (const float*)d_in[3];
    const float* aD   = (const float*)d_in[4];
    const float* bias = (const float*)d_in[5];
    float*       out  = (float*)d_out;

    const int tc_smem_bytes = 128 * 136 * (int)sizeof(float);  // 69632 B
    cudaFuncSetAttribute(k_gemm_tc, cudaFuncAttributeMaxDynamicSharedMemorySize,
                         tc_smem_bytes);

    k_gemm_tc<<<296, 256, tc_smem_bytes>>>(x, W, aS, aD, ei);      // idx 0
    k_scanA<<<NB, 256>>>();                                        // idx 1
    k_scanC<<<NB, 256>>>();                                        // idx 2
    k_scatter<<<(N_EDGES + 255) / 256, 256>>>(ei, x);              // idx 3 (profiled)
    k_agg<<<(N_NODES * 32 + 255) / 256, 256>>>(bias, out);         // idx 4
}